// round 2
// baseline (speedup 1.0000x reference)
#include <cuda_runtime.h>
#include <cstdint>

#define H_DIM 1024
#define M_DIM 512
#define NEXP  8
#define MAX_T 16384

#define BM 128
#define BN 128
#define BK 16
#define LDA 132   // padded to break bank conflicts on transposed A stores

// Scratch (static device globals — no runtime allocation)
__device__ float g_h[MAX_T * M_DIM];     // router hidden activations (32 MB)
__device__ int   g_eid[MAX_T];
__device__ int   g_sorted[MAX_T];
__device__ int   g_cnt[NEXP];
__device__ int   g_off[NEXP];
__device__ int   g_cur[NEXP];

typedef unsigned long long u64;

// Packed fp32x2 FMA (Blackwell paired fp32 pipe — 2x FFMA throughput)
__device__ __forceinline__ void fma2(u64 &d, u64 a, u64 b) {
    asm("fma.rn.f32x2 %0, %1, %2, %0;" : "+l"(d) : "l"(a), "l"(b));
}
__device__ __forceinline__ u64 dup2(float x) {
    unsigned u = __float_as_uint(x);
    return (u64)u | ((u64)u << 32);
}
__device__ __forceinline__ float lo32(u64 v) { return __uint_as_float((unsigned)(v & 0xffffffffu)); }
__device__ __forceinline__ float hi32(u64 v) { return __uint_as_float((unsigned)(v >> 32)); }

// ---------------------------------------------------------------------------
// Kernel 0: zero counters (must run every launch — graph replays)
// ---------------------------------------------------------------------------
__global__ void zero_kernel() {
    int i = threadIdx.x;
    if (i < NEXP) { g_cnt[i] = 0; g_cur[i] = 0; }
}

// ---------------------------------------------------------------------------
// Kernel 1: h = relu(X @ w1 + b1)   [16384,1024]@[1024,512]
// ---------------------------------------------------------------------------
__global__ __launch_bounds__(256) void gemm1_kernel(
    const float* __restrict__ X, const float* __restrict__ w1,
    const float* __restrict__ b1)
{
    __shared__ float As[BK][LDA];
    __shared__ float Bs[BK][BN];
    int tid = threadIdx.x;
    int m0 = blockIdx.y * BM;
    int n0 = blockIdx.x * BN;
    int ty = tid >> 4, tx = tid & 15;

    u64 acc[8][4];
    #pragma unroll
    for (int i = 0; i < 8; i++)
        #pragma unroll
        for (int j = 0; j < 4; j++) acc[i][j] = 0ull;

    for (int k0 = 0; k0 < H_DIM; k0 += BK) {
        #pragma unroll
        for (int l = 0; l < 2; l++) {           // A: 128x16, transposed store
            int idx = tid * 2 + l;
            int row = idx >> 2, c4 = idx & 3;
            float4 v = *(const float4*)&X[(size_t)(m0 + row) * H_DIM + k0 + c4 * 4];
            As[c4*4+0][row] = v.x; As[c4*4+1][row] = v.y;
            As[c4*4+2][row] = v.z; As[c4*4+3][row] = v.w;
        }
        #pragma unroll
        for (int l = 0; l < 2; l++) {           // B: 16x128
            int idx = tid * 2 + l;
            int kr = idx >> 5, c4 = idx & 31;
            *(float4*)&Bs[kr][c4*4] =
                *(const float4*)&w1[(size_t)(k0 + kr) * M_DIM + n0 + c4 * 4];
        }
        __syncthreads();
        #pragma unroll
        for (int kk = 0; kk < BK; kk++) {
            float4 a0 = *(float4*)&As[kk][ty*8];
            float4 a1 = *(float4*)&As[kk][ty*8 + 4];
            const u64* bsp = (const u64*)&Bs[kk][tx*8];
            u64 bp0 = bsp[0], bp1 = bsp[1], bp2 = bsp[2], bp3 = bsp[3];
            float av[8] = {a0.x,a0.y,a0.z,a0.w,a1.x,a1.y,a1.z,a1.w};
            #pragma unroll
            for (int i = 0; i < 8; i++) {
                u64 ad = dup2(av[i]);
                fma2(acc[i][0], ad, bp0);
                fma2(acc[i][1], ad, bp1);
                fma2(acc[i][2], ad, bp2);
                fma2(acc[i][3], ad, bp3);
            }
        }
        __syncthreads();
    }
    #pragma unroll
    for (int i = 0; i < 8; i++) {
        int m = m0 + ty*8 + i;
        float* hr = &g_h[(size_t)m * M_DIM + n0 + tx*8];
        #pragma unroll
        for (int j = 0; j < 4; j++) {
            int n = n0 + tx*8 + j*2;
            float2 o;
            o.x = fmaxf(lo32(acc[i][j]) + b1[n],     0.f);
            o.y = fmaxf(hi32(acc[i][j]) + b1[n + 1], 0.f);
            *(float2*)&hr[j*2] = o;
        }
    }
}

// ---------------------------------------------------------------------------
// Kernel 2: routing scores + argmax (softmax is monotone -> argmax of scores)
// one warp per token
// ---------------------------------------------------------------------------
__global__ __launch_bounds__(256) void route_kernel(
    const float* __restrict__ w2, const float* __restrict__ b2)
{
    __shared__ float w2s[M_DIM * NEXP];
    for (int i = threadIdx.x; i < M_DIM * NEXP; i += 256) w2s[i] = w2[i];
    __syncthreads();

    int warp = threadIdx.x >> 5, lane = threadIdx.x & 31;
    int t = blockIdx.x * 8 + warp;
    const float* hrow = &g_h[(size_t)t * M_DIM];

    float s[NEXP];
    #pragma unroll
    for (int e = 0; e < NEXP; e++) s[e] = 0.f;
    for (int m = lane; m < M_DIM; m += 32) {
        float hv = hrow[m];
        #pragma unroll
        for (int e = 0; e < NEXP; e++) s[e] += hv * w2s[m * NEXP + e];
    }
    #pragma unroll
    for (int o = 16; o > 0; o >>= 1)
        #pragma unroll
        for (int e = 0; e < NEXP; e++)
            s[e] += __shfl_xor_sync(0xffffffff, s[e], o);

    if (lane == 0) {
        int best = 0; float bv = s[0] + b2[0];
        #pragma unroll
        for (int e = 1; e < NEXP; e++) {
            float v = s[e] + b2[e];
            if (v > bv) { bv = v; best = e; }   // strict '>' = first-max, matches argmax
        }
        g_eid[t] = best;
        atomicAdd(&g_cnt[best], 1);
    }
}

// ---------------------------------------------------------------------------
// Kernel 3: prefix over 8 expert counts
// ---------------------------------------------------------------------------
__global__ void prefix_kernel() {
    if (threadIdx.x == 0) {
        int o = 0;
        for (int e = 0; e < NEXP; e++) { g_off[e] = o; o += g_cnt[e]; }
    }
}

// ---------------------------------------------------------------------------
// Kernel 4: scatter token ids into expert-sorted order
// ---------------------------------------------------------------------------
__global__ void scatter_kernel(int NT) {
    int t = blockIdx.x * 256 + threadIdx.x;
    if (t >= NT) return;
    int e = g_eid[t];
    int pos = g_off[e] + atomicAdd(&g_cur[e], 1);
    g_sorted[pos] = t;
}

// ---------------------------------------------------------------------------
// Kernel 5: grouped expert GEMM: out[t] = X[t] @ W[e(t)] + b[e(t)]
// grid: (n-tiles=8, expert=8, token-tile up to NT/BM), early-exit past count
// ---------------------------------------------------------------------------
__global__ __launch_bounds__(256) void expert_gemm_kernel(
    const float* __restrict__ X, const float* __restrict__ eW,
    const float* __restrict__ eb, float* __restrict__ out)
{
    int e    = blockIdx.y;
    int cnt  = g_cnt[e];
    int tile0 = blockIdx.z * BM;
    if (tile0 >= cnt) return;
    int seg = g_off[e];
    int n0  = blockIdx.x * BN;

    __shared__ int   tok[BM];
    __shared__ float As[BK][LDA];
    __shared__ float Bs[BK][BN];

    int tid = threadIdx.x;
    if (tid < BM) {
        int p = tile0 + tid;
        tok[tid] = g_sorted[seg + min(p, cnt - 1)];   // clamp pad rows
    }
    __syncthreads();

    const float* W = eW + (size_t)e * H_DIM * H_DIM;
    int ty = tid >> 4, tx = tid & 15;

    u64 acc[8][4];
    #pragma unroll
    for (int i = 0; i < 8; i++)
        #pragma unroll
        for (int j = 0; j < 4; j++) acc[i][j] = 0ull;

    for (int k0 = 0; k0 < H_DIM; k0 += BK) {
        #pragma unroll
        for (int l = 0; l < 2; l++) {          // A: gathered rows
            int idx = tid * 2 + l;
            int row = idx >> 2, c4 = idx & 3;
            float4 v = *(const float4*)&X[(size_t)tok[row] * H_DIM + k0 + c4 * 4];
            As[c4*4+0][row] = v.x; As[c4*4+1][row] = v.y;
            As[c4*4+2][row] = v.z; As[c4*4+3][row] = v.w;
        }
        #pragma unroll
        for (int l = 0; l < 2; l++) {          // B: W[k][n], stride 1024
            int idx = tid * 2 + l;
            int kr = idx >> 5, c4 = idx & 31;
            *(float4*)&Bs[kr][c4*4] =
                *(const float4*)&W[(size_t)(k0 + kr) * H_DIM + n0 + c4 * 4];
        }
        __syncthreads();
        #pragma unroll
        for (int kk = 0; kk < BK; kk++) {
            float4 a0 = *(float4*)&As[kk][ty*8];
            float4 a1 = *(float4*)&As[kk][ty*8 + 4];
            const u64* bsp = (const u64*)&Bs[kk][tx*8];
            u64 bp0 = bsp[0], bp1 = bsp[1], bp2 = bsp[2], bp3 = bsp[3];
            float av[8] = {a0.x,a0.y,a0.z,a0.w,a1.x,a1.y,a1.z,a1.w};
            #pragma unroll
            for (int i = 0; i < 8; i++) {
                u64 ad = dup2(av[i]);
                fma2(acc[i][0], ad, bp0);
                fma2(acc[i][1], ad, bp1);
                fma2(acc[i][2], ad, bp2);
                fma2(acc[i][3], ad, bp3);
            }
        }
        __syncthreads();
    }

    #pragma unroll
    for (int i = 0; i < 8; i++) {
        int p = tile0 + ty*8 + i;
        if (p < cnt) {
            int t = tok[ty*8 + i];
            float* orow = &out[(size_t)t * H_DIM + n0 + tx*8];
            const float* brow = &eb[(size_t)e * H_DIM + n0 + tx*8];
            #pragma unroll
            for (int j = 0; j < 4; j++) {
                float2 o;
                o.x = lo32(acc[i][j]) + brow[j*2];
                o.y = hi32(acc[i][j]) + brow[j*2 + 1];
                *(float2*)&orow[j*2] = o;
            }
        }
    }
}

// ---------------------------------------------------------------------------
extern "C" void kernel_launch(void* const* d_in, const int* in_sizes, int n_in,
                              void* d_out, int out_size)
{
    const float* X  = (const float*)d_in[0];   // hidden_states [4,4096,1024]
    const float* w1 = (const float*)d_in[1];   // [1024,512]
    const float* b1 = (const float*)d_in[2];   // [512]
    const float* w2 = (const float*)d_in[3];   // [512,8]
    const float* b2 = (const float*)d_in[4];   // [8]
    const float* eW = (const float*)d_in[5];   // [8,1024,1024]
    const float* eb = (const float*)d_in[6];   // [8,1024]
    float* out = (float*)d_out;

    int NT = in_sizes[0] / H_DIM;              // 16384 tokens

    zero_kernel<<<1, 32>>>();

    dim3 g1(M_DIM / BN, NT / BM);              // (4, 128)
    gemm1_kernel<<<g1, 256>>>(X, w1, b1);

    route_kernel<<<NT / 8, 256>>>(w2, b2);
    prefix_kernel<<<1, 32>>>();
    scatter_kernel<<<(NT + 255) / 256, 256>>>(NT);

    dim3 g2(H_DIM / BN, NEXP, NT / BM);        // (8, 8, 128) — most z-tiles early-exit
    expert_gemm_kernel<<<g2, 256>>>(X, eW, eb, out);
}

// round 4
// speedup vs baseline: 1.2189x; 1.2189x over previous
#include <cuda_runtime.h>
#include <cuda_fp16.h>
#include <cstdint>

#define NT    16384
#define HD    1024
#define MD    512
#define NEXP  8

#define BM    128
#define BN    128
#define BK    32
#define NITER (HD / BK)       // 32
#define LDS   40              // smem row stride in halves (32 + 8 pad -> conflict-free ldmatrix)
#define STG_BYTES (BM * LDS * 2)  // 10240 per stage per tile

// ---------------------------------------------------------------------------
// Static device scratch
// ---------------------------------------------------------------------------
__device__ float  g_h[NT * MD];                    // router hidden (fp32)
__device__ __half g_xh[NT * HD];                   // X in fp16
__device__ __half g_w1t[MD * HD];                  // w1^T [n][k] fp16
__device__ __half g_wt[NEXP * HD * HD];            // W^T  [e][n][k] fp16
__device__ int g_eid[NT], g_sorted[NT], g_cnt[NEXP], g_off[NEXP], g_cur[NEXP];

// ---------------------------------------------------------------------------
// PTX helpers (compute_103-baseline only: cp.async / ldmatrix / mma.sync)
// ---------------------------------------------------------------------------
__device__ __forceinline__ uint32_t smem_u32(const void* p) {
    uint32_t a;
    asm("{ .reg .u64 t; cvta.to.shared.u64 t, %1; cvt.u32.u64 %0, t; }" : "=r"(a) : "l"(p));
    return a;
}
#define CP16(sm, gm) \
    asm volatile("cp.async.cg.shared.global [%0], [%1], 16;" :: "r"(sm), "l"(gm))
#define CP_COMMIT() asm volatile("cp.async.commit_group;")
#define CP_WAIT1()  asm volatile("cp.async.wait_group 1;")
#define CP_WAIT0()  asm volatile("cp.async.wait_group 0;")

#define LDM4(r, a) \
    asm volatile("ldmatrix.sync.aligned.m8n8.x4.shared.b16 {%0,%1,%2,%3}, [%4];" \
        : "=r"((r)[0]), "=r"((r)[1]), "=r"((r)[2]), "=r"((r)[3]) : "r"(a))

#define MMA16816(d, a, b0, b1) \
    asm volatile("mma.sync.aligned.m16n8k16.row.col.f32.f16.f16.f32 " \
        "{%0,%1,%2,%3}, {%4,%5,%6,%7}, {%8,%9}, {%0,%1,%2,%3};" \
        : "+f"((d)[0]), "+f"((d)[1]), "+f"((d)[2]), "+f"((d)[3]) \
        : "r"((a)[0]), "r"((a)[1]), "r"((a)[2]), "r"((a)[3]), "r"(b0), "r"(b1))

// ---------------------------------------------------------------------------
// Setup kernels
// ---------------------------------------------------------------------------
__global__ void zero_kernel() {
    int i = threadIdx.x;
    if (i < NEXP) { g_cnt[i] = 0; g_cur[i] = 0; }
}

// X fp32 -> fp16 (8 elems/thread)
__global__ __launch_bounds__(256) void convx_kernel(const float* __restrict__ X) {
    size_t base = ((size_t)blockIdx.x * 256 + threadIdx.x) * 8;
    float4 v0 = *(const float4*)(X + base);
    float4 v1 = *(const float4*)(X + base + 4);
    __half2* d = (__half2*)(g_xh + base);
    d[0] = __floats2half2_rn(v0.x, v0.y);
    d[1] = __floats2half2_rn(v0.z, v0.w);
    d[2] = __floats2half2_rn(v1.x, v1.y);
    d[3] = __floats2half2_rn(v1.z, v1.w);
}

// src fp32 [e][HD][ncols] -> dst fp16 [e][n][HD]  (transpose + convert)
__global__ __launch_bounds__(256) void transconv_kernel(
    const float* __restrict__ src, __half* __restrict__ dst, int ncols)
{
    __shared__ float t[32][33];
    int e = blockIdx.z;
    const float* S = src + (size_t)e * HD * ncols;
    __half* D = dst + (size_t)e * HD * ncols;
    int nb = blockIdx.x * 32, kb = blockIdx.y * 32;
    int lx = threadIdx.x & 31, ly = threadIdx.x >> 5;
    #pragma unroll
    for (int i = 0; i < 4; i++)
        t[ly + i * 8][lx] = S[(size_t)(kb + ly + i * 8) * ncols + nb + lx];
    __syncthreads();
    #pragma unroll
    for (int i = 0; i < 4; i++) {
        int n = nb + ly + i * 8, k = kb + lx;
        D[(size_t)n * HD + k] = __float2half_rn(t[lx][ly + i * 8]);
    }
}

// ---------------------------------------------------------------------------
// fp16 mma.sync GEMM: out[row,n] = sum_k A[row,k]*B^T[n,k] (+bias, opt relu)
// A rows optionally gathered via g_sorted; per-expert B/bias via blockIdx.y.
// 128x128x32 CTA tile, 8 warps (2x4), 64x32 warp tile, 2-stage cp.async.
// ---------------------------------------------------------------------------
template<bool GATHER, bool RELU>
__global__ __launch_bounds__(256, 2) void mma_gemm_kernel(
    const __half* __restrict__ Ag, const __half* __restrict__ Bg,
    const float* __restrict__ bias, float* __restrict__ out,
    int ostride, int npe)
{
    __shared__ __align__(16) __half As[2][BM * LDS];
    __shared__ __align__(16) __half Bs[2][BN * LDS];
    __shared__ int tokS[BM];

    int tid = threadIdx.x, lane = tid & 31, wid = tid >> 5;
    int e = blockIdx.y;
    int tile0 = blockIdx.z * BM;
    int n0 = blockIdx.x * BN;

    int cnt = NT, seg = 0;
    if (GATHER) {
        cnt = g_cnt[e];
        if (tile0 >= cnt) return;
        seg = g_off[e];
        if (tid < BM) tokS[tid] = g_sorted[seg + min(tile0 + tid, cnt - 1)];
        __syncthreads();
    }

    // cp.async load mapping: 2 x 16B per thread per tile per stage
    int idx0 = tid, idx1 = tid + 256;
    int r0 = idx0 >> 2, c0 = idx0 & 3, r1 = idx1 >> 2, c1 = idx1 & 3;
    int ar0 = GATHER ? tokS[r0] : (tile0 + r0);
    int ar1 = GATHER ? tokS[r1] : (tile0 + r1);
    const __half* gA0 = Ag + (size_t)ar0 * HD + c0 * 8;
    const __half* gA1 = Ag + (size_t)ar1 * HD + c1 * 8;
    const __half* Bbase = Bg + (size_t)e * npe * HD;
    const __half* gB0 = Bbase + (size_t)(n0 + r0) * HD + c0 * 8;
    const __half* gB1 = Bbase + (size_t)(n0 + r1) * HD + c1 * 8;

    uint32_t sAbase = smem_u32(As), sBbase = smem_u32(Bs);
    uint32_t sA0 = sAbase + (r0 * LDS + c0 * 8) * 2;
    uint32_t sA1 = sAbase + (r1 * LDS + c1 * 8) * 2;
    uint32_t sB0 = sBbase + (r0 * LDS + c0 * 8) * 2;
    uint32_t sB1 = sBbase + (r1 * LDS + c1 * 8) * 2;

    // warp tiling: 2 warps along M (64 rows each), 4 along N (32 cols each)
    int wm = wid & 1, wn = wid >> 1;
    uint32_t aLd = sAbase + ((wm * 64 + (lane & 15)) * LDS + ((lane >> 4) << 3)) * 2;
    uint32_t bLd = sBbase + ((wn * 32 + (lane & 7) + ((lane & 16) ? 8 : 0)) * LDS
                             + ((lane & 8) ? 8 : 0)) * 2;

    float acc[4][4][4];
    #pragma unroll
    for (int i = 0; i < 4; i++)
        #pragma unroll
        for (int j = 0; j < 4; j++)
            #pragma unroll
            for (int q = 0; q < 4; q++) acc[i][j][q] = 0.f;

    // prefetch stage 0
    CP16(sA0, gA0); CP16(sA1, gA1);
    CP16(sB0, gB0); CP16(sB1, gB1);
    CP_COMMIT();

    for (int cch = 0; cch < NITER; cch++) {
        int buf = cch & 1;
        if (cch + 1 < NITER) {
            int nb = (cch + 1) & 1;
            int koff = (cch + 1) * BK;
            uint32_t so = nb * STG_BYTES;
            CP16(sA0 + so, gA0 + koff); CP16(sA1 + so, gA1 + koff);
            CP16(sB0 + so, gB0 + koff); CP16(sB1 + so, gB1 + koff);
            CP_COMMIT();
            CP_WAIT1();
        } else {
            CP_WAIT0();
        }
        __syncthreads();

        uint32_t aB = aLd + buf * STG_BYTES;
        uint32_t bB = bLd + buf * STG_BYTES;
        #pragma unroll
        for (int kk = 0; kk < BK; kk += 16) {
            uint32_t ar[4][4], br[2][4];
            #pragma unroll
            for (int mi = 0; mi < 4; mi++)
                LDM4(ar[mi], aB + (mi * 16 * LDS + kk) * 2);
            #pragma unroll
            for (int p = 0; p < 2; p++)
                LDM4(br[p], bB + (p * 16 * LDS + kk) * 2);
            #pragma unroll
            for (int mi = 0; mi < 4; mi++) {
                #pragma unroll
                for (int nj = 0; nj < 4; nj++) {
                    uint32_t b0 = br[nj >> 1][(nj & 1) * 2];
                    uint32_t b1 = br[nj >> 1][(nj & 1) * 2 + 1];
                    MMA16816(acc[mi][nj], ar[mi], b0, b1);
                }
            }
        }
        __syncthreads();
    }

    // Epilogue: bias add (+relu), scatter rows
    const float* bptr = bias + (size_t)e * npe;
    int qrow = lane >> 2, qcol = (lane & 3) * 2;
    #pragma unroll
    for (int mi = 0; mi < 4; mi++) {
        #pragma unroll
        for (int half = 0; half < 2; half++) {
            int mrow = wm * 64 + mi * 16 + qrow + half * 8;
            bool valid = (tile0 + mrow) < cnt;
            if (!valid) continue;
            int orow = GATHER ? tokS[mrow] : (tile0 + mrow);
            float* orp = out + (size_t)orow * ostride + n0;
            #pragma unroll
            for (int nj = 0; nj < 4; nj++) {
                int coln = wn * 32 + nj * 8 + qcol;
                float2 bv = *(const float2*)(bptr + n0 + coln);
                float2 ov;
                ov.x = acc[mi][nj][half * 2 + 0] + bv.x;
                ov.y = acc[mi][nj][half * 2 + 1] + bv.y;
                if (RELU) { ov.x = fmaxf(ov.x, 0.f); ov.y = fmaxf(ov.y, 0.f); }
                *(float2*)(orp + coln) = ov;
            }
        }
    }
}

// ---------------------------------------------------------------------------
// Routing: scores from approx h, argmax; near-ties recomputed exactly in fp32
// ---------------------------------------------------------------------------
#define TAU 1e-2f
__global__ __launch_bounds__(256) void route_kernel(
    const float* __restrict__ X,  const float* __restrict__ w1,
    const float* __restrict__ b1, const float* __restrict__ w2,
    const float* __restrict__ b2)
{
    __shared__ float w2s[MD * NEXP];
    for (int i = threadIdx.x; i < MD * NEXP; i += 256) w2s[i] = w2[i];
    __syncthreads();

    int warp = threadIdx.x >> 5, lane = threadIdx.x & 31;
    int t = blockIdx.x * 8 + warp;
    const float* hrow = &g_h[(size_t)t * MD];

    float s[NEXP];
    #pragma unroll
    for (int e = 0; e < NEXP; e++) s[e] = 0.f;
    for (int m = lane; m < MD; m += 32) {
        float hv = hrow[m];
        #pragma unroll
        for (int e = 0; e < NEXP; e++) s[e] += hv * w2s[m * NEXP + e];
    }
    #pragma unroll
    for (int o = 16; o > 0; o >>= 1)
        #pragma unroll
        for (int e = 0; e < NEXP; e++)
            s[e] += __shfl_xor_sync(0xffffffff, s[e], o);

    int need = 0, best = 0;
    if (lane == 0) {
        float v1 = -1e30f, v2 = -1e30f;
        #pragma unroll
        for (int e = 0; e < NEXP; e++) {
            float v = s[e] + b2[e];
            if (v > v1) { v2 = v1; v1 = v; best = e; }
            else if (v > v2) v2 = v;
        }
        need = (v1 - v2 < TAU) ? 1 : 0;
    }
    need = __shfl_sync(0xffffffff, need, 0);

    if (need) {
        float hl[16];
        #pragma unroll
        for (int j = 0; j < 16; j++) hl[j] = b1[lane * 16 + j];
        const float* xr = &X[(size_t)t * HD];
        for (int k = 0; k < HD; k++) {
            float xv = xr[k];
            const float* wr = &w1[(size_t)k * MD + lane * 16];
            #pragma unroll
            for (int j = 0; j < 16; j++) hl[j] += xv * wr[j];
        }
        float sr[NEXP];
        #pragma unroll
        for (int e = 0; e < NEXP; e++) sr[e] = 0.f;
        #pragma unroll
        for (int j = 0; j < 16; j++) {
            float hv = fmaxf(hl[j], 0.f);
            const float* wc = &w2s[(lane * 16 + j) * NEXP];
            #pragma unroll
            for (int e = 0; e < NEXP; e++) sr[e] += hv * wc[e];
        }
        #pragma unroll
        for (int o = 16; o > 0; o >>= 1)
            #pragma unroll
            for (int e = 0; e < NEXP; e++)
                sr[e] += __shfl_xor_sync(0xffffffff, sr[e], o);
        if (lane == 0) {
            float bv = sr[0] + b2[0]; best = 0;
            #pragma unroll
            for (int e = 1; e < NEXP; e++) {
                float v = sr[e] + b2[e];
                if (v > bv) { bv = v; best = e; }
            }
        }
    }
    if (lane == 0) {
        g_eid[t] = best;
        atomicAdd(&g_cnt[best], 1);
    }
}

__global__ void prefix_kernel() {
    if (threadIdx.x == 0) {
        int o = 0;
        for (int e = 0; e < NEXP; e++) { g_off[e] = o; o += g_cnt[e]; }
    }
}
__global__ void scatter_kernel(int ntok) {
    int t = blockIdx.x * 256 + threadIdx.x;
    if (t >= ntok) return;
    int e = g_eid[t];
    int pos = g_off[e] + atomicAdd(&g_cur[e], 1);
    g_sorted[pos] = t;
}

// ---------------------------------------------------------------------------
extern "C" void kernel_launch(void* const* d_in, const int* in_sizes, int n_in,
                              void* d_out, int out_size)
{
    const float* X  = (const float*)d_in[0];
    const float* w1 = (const float*)d_in[1];
    const float* b1 = (const float*)d_in[2];
    const float* w2 = (const float*)d_in[3];
    const float* b2 = (const float*)d_in[4];
    const float* eW = (const float*)d_in[5];
    const float* eb = (const float*)d_in[6];
    float* out = (float*)d_out;

    __half *xh, *w1t, *wt;
    float* hbuf;
    cudaGetSymbolAddress((void**)&xh,   g_xh);
    cudaGetSymbolAddress((void**)&w1t,  g_w1t);
    cudaGetSymbolAddress((void**)&wt,   g_wt);
    cudaGetSymbolAddress((void**)&hbuf, g_h);

    zero_kernel<<<1, 32>>>();
    convx_kernel<<<NT * HD / 2048, 256>>>(X);
    transconv_kernel<<<dim3(MD / 32, HD / 32, 1), 256>>>(w1, w1t, MD);
    transconv_kernel<<<dim3(HD / 32, HD / 32, NEXP), 256>>>(eW, wt, HD);

    // router GEMM1: h = relu(X @ w1 + b1) -> g_h
    mma_gemm_kernel<false, true><<<dim3(MD / BN, 1, NT / BM), 256>>>(
        xh, w1t, b1, hbuf, MD, MD);

    route_kernel<<<NT / 8, 256>>>(X, w1, b1, w2, b2);
    prefix_kernel<<<1, 32>>>();
    scatter_kernel<<<(NT + 255) / 256, 256>>>(NT);

    // grouped expert GEMM: out = gather(X) @ W[e]^T + b[e]
    mma_gemm_kernel<true, false><<<dim3(HD / BN, NEXP, NT / BM), 256>>>(
        xh, wt, eb, out, HD, HD);
}